// round 1
// baseline (speedup 1.0000x reference)
#include <cuda_runtime.h>
#include <math.h>

#define NS 50000
#define NA 50000
#define NEDGE 1600000

// Scratch (device globals; no allocation allowed)
__device__ __align__(16) float g_Apre[NA * 32];   // a2s src-side layer1 partial (+b1)
__device__ __align__(16) float g_Bpre[NS * 32];   // a2s dst-side layer1 partial
__device__ __align__(16) float g_Cpre[NS * 32];   // s2s src-side layer1 partial (+b1)
__device__ __align__(16) float g_Dpre[NS * 32];   // s2s dst-side layer1 partial
__device__ __align__(16) float g_sum_u[NS * 64];
__device__ __align__(16) float g_sum_h[NS * 64];

__device__ __forceinline__ float leaky(float x) { return x > 0.f ? x : 0.01f * x; }

// ---------------------------------------------------------------------------
// Per-state-node: Bpre (a2s dst part), Dpre (s2s dst part), zero the sum bufs.
// warp per node, lane = hidden index j in [0,32)
// ---------------------------------------------------------------------------
__global__ void __launch_bounds__(256) pre_s_kernel(
    const float* __restrict__ pos_s,
    const float* __restrict__ a2s_W1,
    const float* __restrict__ s2s_W1)
{
    int lane = threadIdx.x & 31;
    int node = (blockIdx.x * blockDim.x + threadIdx.x) >> 5;
    if (node >= NS) return;
    float p0 = __ldg(pos_s + 2 * node);
    float p1 = __ldg(pos_s + 2 * node + 1);
    g_Bpre[node * 32 + lane] =
        p0 * __ldg(a2s_W1 + 2 * 32 + lane) + p1 * __ldg(a2s_W1 + 3 * 32 + lane);
    g_Dpre[node * 32 + lane] =
        p0 * __ldg(s2s_W1 + 2 * 32 + lane) + p1 * __ldg(s2s_W1 + 3 * 32 + lane);
    g_sum_u[node * 64 + lane]      = 0.f;
    g_sum_u[node * 64 + 32 + lane] = 0.f;
    g_sum_h[node * 64 + lane]      = 0.f;
    g_sum_h[node * 64 + 32 + lane] = 0.f;
}

// ---------------------------------------------------------------------------
// Per-action-node: Apre = b1 + pos_a@W1[0:2] + u@W1[5:21]
// ---------------------------------------------------------------------------
__global__ void __launch_bounds__(256) pre_a2s_kernel(
    const float* __restrict__ pos_a,
    const float* __restrict__ u,
    const float* __restrict__ W1,
    const float* __restrict__ b1)
{
    int lane = threadIdx.x & 31;
    int node = (blockIdx.x * blockDim.x + threadIdx.x) >> 5;
    if (node >= NA) return;
    float p0 = __ldg(pos_a + 2 * node);
    float p1 = __ldg(pos_a + 2 * node + 1);
    float acc = __ldg(b1 + lane)
              + p0 * __ldg(W1 + 0 * 32 + lane)
              + p1 * __ldg(W1 + 1 * 32 + lane);
    const float4* u4 = reinterpret_cast<const float4*>(u) + node * 4;
#pragma unroll
    for (int q = 0; q < 4; ++q) {
        float4 v = __ldg(u4 + q);
        acc = fmaf(v.x, __ldg(W1 + (5 + 4 * q + 0) * 32 + lane), acc);
        acc = fmaf(v.y, __ldg(W1 + (5 + 4 * q + 1) * 32 + lane), acc);
        acc = fmaf(v.z, __ldg(W1 + (5 + 4 * q + 2) * 32 + lane), acc);
        acc = fmaf(v.w, __ldg(W1 + (5 + 4 * q + 3) * 32 + lane), acc);
    }
    g_Apre[node * 32 + lane] = acc;
}

// ---------------------------------------------------------------------------
// Per-state-node: Cpre = b1 + pos_s@W1[0:2] + h@W1[5:69]
// ---------------------------------------------------------------------------
__global__ void __launch_bounds__(256) pre_s2s_kernel(
    const float* __restrict__ pos_s,
    const float* __restrict__ h,
    const float* __restrict__ W1,
    const float* __restrict__ b1)
{
    int lane = threadIdx.x & 31;
    int node = (blockIdx.x * blockDim.x + threadIdx.x) >> 5;
    if (node >= NS) return;
    float p0 = __ldg(pos_s + 2 * node);
    float p1 = __ldg(pos_s + 2 * node + 1);
    float acc = __ldg(b1 + lane)
              + p0 * __ldg(W1 + 0 * 32 + lane)
              + p1 * __ldg(W1 + 1 * 32 + lane);
    const float4* h4 = reinterpret_cast<const float4*>(h) + node * 16;
#pragma unroll
    for (int q = 0; q < 16; ++q) {
        float4 v = __ldg(h4 + q);
        acc = fmaf(v.x, __ldg(W1 + (5 + 4 * q + 0) * 32 + lane), acc);
        acc = fmaf(v.y, __ldg(W1 + (5 + 4 * q + 1) * 32 + lane), acc);
        acc = fmaf(v.z, __ldg(W1 + (5 + 4 * q + 2) * 32 + lane), acc);
        acc = fmaf(v.w, __ldg(W1 + (5 + 4 * q + 3) * 32 + lane), acc);
    }
    g_Cpre[node * 32 + lane] = acc;
}

// ---------------------------------------------------------------------------
// Edge kernel: warp per CHUNK edges. Per edge:
//   hid[32] = leaky(Asrc[src] + Bdst[dst] + dis*W1[4,:])
//   msg[64] = tanh(hid @ W2 + b2)
//   red.global.add.v2.f32 scatter into sum buffer at dst.
// Lane j owns output columns (2j, 2j+1). W2 lives in registers (64/lane).
// ---------------------------------------------------------------------------
template <int WHICH>
__global__ void __launch_bounds__(256) edge_kernel(
    const int* __restrict__ src, const int* __restrict__ dst,
    const float* __restrict__ dis,
    const float* __restrict__ W1,
    const float* __restrict__ W2,
    const float* __restrict__ b2)
{
    const float* __restrict__ Asrc = (WHICH == 0) ? g_Apre : g_Cpre;
    const float* __restrict__ Bdst = (WHICH == 0) ? g_Bpre : g_Dpre;
    float* __restrict__ sumbuf     = (WHICH == 0) ? g_sum_u : g_sum_h;

    const int CHUNK = 64;
    int lane = threadIdx.x & 31;
    int warp = (blockIdx.x * blockDim.x + threadIdx.x) >> 5;
    int base = warp * CHUNK;
    if (base >= NEDGE) return;

    float w1d = __ldg(W1 + 4 * 32 + lane);
    float w2a[32], w2b[32];
#pragma unroll
    for (int k = 0; k < 32; ++k) {
        float2 wv = __ldg(reinterpret_cast<const float2*>(W2 + k * 64) + lane);
        w2a[k] = wv.x;
        w2b[k] = wv.y;
    }
    float b2a = __ldg(b2 + 2 * lane);
    float b2b = __ldg(b2 + 2 * lane + 1);

    for (int e0 = 0; e0 < CHUNK; e0 += 32) {
        int nv = NEDGE - (base + e0);
        if (nv <= 0) break;
        if (nv > 32) nv = 32;
        int eidx = base + e0 + lane;
        int s = 0, d = 0;
        float dv = 0.f;
        if (lane < nv) {
            s  = __ldg(src + eidx);
            d  = __ldg(dst + eidx);
            dv = __ldg(dis + eidx);
        }
        for (int t = 0; t < nv; ++t) {
            int ss   = __shfl_sync(0xffffffffu, s, t);
            int dd   = __shfl_sync(0xffffffffu, d, t);
            float dw = __shfl_sync(0xffffffffu, dv, t);
            float hid = __ldg(Asrc + ss * 32 + lane)
                      + __ldg(Bdst + dd * 32 + lane)
                      + dw * w1d;
            hid = leaky(hid);
            float m0 = b2a, m1 = b2b;
#pragma unroll
            for (int k = 0; k < 32; ++k) {
                float hv = __shfl_sync(0xffffffffu, hid, k);
                m0 = fmaf(hv, w2a[k], m0);
                m1 = fmaf(hv, w2b[k], m1);
            }
            m0 = tanhf(m0);
            m1 = tanhf(m1);
            float* p = sumbuf + dd * 64 + 2 * lane;
            asm volatile("red.global.add.v2.f32 [%0], {%1, %2};"
                         :: "l"(p), "f"(m0), "f"(m1) : "memory");
        }
    }
}

// ---------------------------------------------------------------------------
// Node update: [pos_s(2), h(64), sum_u(64), sum_h(64)] -> 32 -> 64, tanh.
// warp per node; lane = hidden j; outputs (2j, 2j+1).
// ---------------------------------------------------------------------------
__global__ void __launch_bounds__(256) upd_kernel(
    const float* __restrict__ pos_s,
    const float* __restrict__ h,
    const float* __restrict__ W1,
    const float* __restrict__ b1,
    const float* __restrict__ W2,
    const float* __restrict__ b2,
    float* __restrict__ out)
{
    int lane = threadIdx.x & 31;
    int node = (blockIdx.x * blockDim.x + threadIdx.x) >> 5;
    if (node >= NS) return;
    float p0 = __ldg(pos_s + 2 * node);
    float p1 = __ldg(pos_s + 2 * node + 1);
    float acc = __ldg(b1 + lane)
              + p0 * __ldg(W1 + 0 * 32 + lane)
              + p1 * __ldg(W1 + 1 * 32 + lane);

    const float4* h4  = reinterpret_cast<const float4*>(h) + node * 16;
    const float4* su4 = reinterpret_cast<const float4*>(g_sum_u) + node * 16;
    const float4* sh4 = reinterpret_cast<const float4*>(g_sum_h) + node * 16;
#pragma unroll
    for (int q = 0; q < 16; ++q) {
        float4 v = __ldg(h4 + q);
        acc = fmaf(v.x, __ldg(W1 + (2 + 4 * q + 0) * 32 + lane), acc);
        acc = fmaf(v.y, __ldg(W1 + (2 + 4 * q + 1) * 32 + lane), acc);
        acc = fmaf(v.z, __ldg(W1 + (2 + 4 * q + 2) * 32 + lane), acc);
        acc = fmaf(v.w, __ldg(W1 + (2 + 4 * q + 3) * 32 + lane), acc);
    }
#pragma unroll
    for (int q = 0; q < 16; ++q) {
        float4 v = su4[q];
        acc = fmaf(v.x, __ldg(W1 + (66 + 4 * q + 0) * 32 + lane), acc);
        acc = fmaf(v.y, __ldg(W1 + (66 + 4 * q + 1) * 32 + lane), acc);
        acc = fmaf(v.z, __ldg(W1 + (66 + 4 * q + 2) * 32 + lane), acc);
        acc = fmaf(v.w, __ldg(W1 + (66 + 4 * q + 3) * 32 + lane), acc);
    }
#pragma unroll
    for (int q = 0; q < 16; ++q) {
        float4 v = sh4[q];
        acc = fmaf(v.x, __ldg(W1 + (130 + 4 * q + 0) * 32 + lane), acc);
        acc = fmaf(v.y, __ldg(W1 + (130 + 4 * q + 1) * 32 + lane), acc);
        acc = fmaf(v.z, __ldg(W1 + (130 + 4 * q + 2) * 32 + lane), acc);
        acc = fmaf(v.w, __ldg(W1 + (130 + 4 * q + 3) * 32 + lane), acc);
    }
    acc = leaky(acc);

    float m0 = __ldg(b2 + 2 * lane);
    float m1 = __ldg(b2 + 2 * lane + 1);
#pragma unroll
    for (int k = 0; k < 32; ++k) {
        float hv = __shfl_sync(0xffffffffu, acc, k);
        float2 wv = __ldg(reinterpret_cast<const float2*>(W2 + k * 64) + lane);
        m0 = fmaf(hv, wv.x, m0);
        m1 = fmaf(hv, wv.y, m1);
    }
    float2 o;
    o.x = tanhf(m0);
    o.y = tanhf(m1);
    reinterpret_cast<float2*>(out)[node * 32 + lane] = o;
}

// ---------------------------------------------------------------------------
extern "C" void kernel_launch(void* const* d_in, const int* in_sizes, int n_in,
                              void* d_out, int out_size)
{
    const float* h        = (const float*)d_in[0];
    const float* u        = (const float*)d_in[1];
    const float* pos_s    = (const float*)d_in[2];
    const float* pos_a    = (const float*)d_in[3];
    const float* dis_a2s  = (const float*)d_in[4];
    const float* dis_s2s  = (const float*)d_in[5];
    const int*   a2s_src  = (const int*)d_in[6];
    const int*   a2s_dst  = (const int*)d_in[7];
    const int*   s2s_src  = (const int*)d_in[8];
    const int*   s2s_dst  = (const int*)d_in[9];
    const float* a2s_W1   = (const float*)d_in[10];
    const float* a2s_b1   = (const float*)d_in[11];
    const float* a2s_W2   = (const float*)d_in[12];
    const float* a2s_b2   = (const float*)d_in[13];
    const float* s2s_W1   = (const float*)d_in[14];
    const float* s2s_b1   = (const float*)d_in[15];
    const float* s2s_W2   = (const float*)d_in[16];
    const float* s2s_b2   = (const float*)d_in[17];
    const float* upd_W1   = (const float*)d_in[18];
    const float* upd_b1   = (const float*)d_in[19];
    const float* upd_W2   = (const float*)d_in[20];
    const float* upd_b2   = (const float*)d_in[21];
    float* out = (float*)d_out;

    const int WPB = 8;  // warps per block (256 threads)

    // Node-side precompute (independent; serialized on stream, all tiny)
    pre_s_kernel  <<<(NS + WPB - 1) / WPB, 256>>>(pos_s, a2s_W1, s2s_W1);
    pre_a2s_kernel<<<(NA + WPB - 1) / WPB, 256>>>(pos_a, u, a2s_W1, a2s_b1);
    pre_s2s_kernel<<<(NS + WPB - 1) / WPB, 256>>>(pos_s, h, s2s_W1, s2s_b1);

    // Edge passes
    const int CHUNK = 64;
    int nwarps = (NEDGE + CHUNK - 1) / CHUNK;
    int eblocks = (nwarps + WPB - 1) / WPB;
    edge_kernel<0><<<eblocks, 256>>>(a2s_src, a2s_dst, dis_a2s, a2s_W1, a2s_W2, a2s_b2);
    edge_kernel<1><<<eblocks, 256>>>(s2s_src, s2s_dst, dis_s2s, s2s_W1, s2s_W2, s2s_b2);

    // Node update
    upd_kernel<<<(NS + WPB - 1) / WPB, 256>>>(pos_s, h, upd_W1, upd_b1, upd_W2, upd_b2, out);
}

// round 2
// speedup vs baseline: 1.4389x; 1.4389x over previous
#include <cuda_runtime.h>
#include <math.h>

#define NS 50000
#define NA 50000
#define NEDGE 1600000

typedef unsigned long long ull;

// Scratch (device globals; no allocation allowed)
__device__ __align__(16) float g_Apre[NA * 32];   // a2s src-side layer1 partial (+b1)
__device__ __align__(16) float g_Bpre[NS * 32];   // a2s dst-side layer1 partial
__device__ __align__(16) float g_Cpre[NS * 32];   // s2s src-side layer1 partial (+b1)
__device__ __align__(16) float g_Dpre[NS * 32];   // s2s dst-side layer1 partial
__device__ __align__(16) float g_sum_u[NS * 64];
__device__ __align__(16) float g_sum_h[NS * 64];

__device__ __forceinline__ float leaky(float x) { return fmaxf(x, 0.01f * x); }

__device__ __forceinline__ ull pack2(float x, float y) {
    ull r; asm("mov.b64 %0, {%1, %2};" : "=l"(r) : "f"(x), "f"(y)); return r;
}
__device__ __forceinline__ void unpack2(ull v, float& x, float& y) {
    asm("mov.b64 {%0, %1}, %2;" : "=f"(x), "=f"(y) : "l"(v));
}
__device__ __forceinline__ ull ffma2(ull a, ull b, ull c) {
    ull r; asm("fma.rn.f32x2 %0, %1, %2, %3;" : "=l"(r) : "l"(a), "l"(b), "l"(c)); return r;
}
__device__ __forceinline__ float tanh_fast(float x) {
    float r; asm("tanh.approx.f32 %0, %1;" : "=f"(r) : "f"(x)); return r;
}

// ---------------------------------------------------------------------------
// Per-state-node: Bpre (a2s dst part), Dpre (s2s dst part), zero the sum bufs.
// ---------------------------------------------------------------------------
__global__ void __launch_bounds__(256) pre_s_kernel(
    const float* __restrict__ pos_s,
    const float* __restrict__ a2s_W1,
    const float* __restrict__ s2s_W1)
{
    int lane = threadIdx.x & 31;
    int node = (blockIdx.x * blockDim.x + threadIdx.x) >> 5;
    if (node >= NS) return;
    float p0 = __ldg(pos_s + 2 * node);
    float p1 = __ldg(pos_s + 2 * node + 1);
    g_Bpre[node * 32 + lane] =
        p0 * __ldg(a2s_W1 + 2 * 32 + lane) + p1 * __ldg(a2s_W1 + 3 * 32 + lane);
    g_Dpre[node * 32 + lane] =
        p0 * __ldg(s2s_W1 + 2 * 32 + lane) + p1 * __ldg(s2s_W1 + 3 * 32 + lane);
    g_sum_u[node * 64 + lane]      = 0.f;
    g_sum_u[node * 64 + 32 + lane] = 0.f;
    g_sum_h[node * 64 + lane]      = 0.f;
    g_sum_h[node * 64 + 32 + lane] = 0.f;
}

// ---------------------------------------------------------------------------
// Per-action-node: Apre = b1 + pos_a@W1[0:2] + u@W1[5:21]
// ---------------------------------------------------------------------------
__global__ void __launch_bounds__(256) pre_a2s_kernel(
    const float* __restrict__ pos_a,
    const float* __restrict__ u,
    const float* __restrict__ W1,
    const float* __restrict__ b1)
{
    int lane = threadIdx.x & 31;
    int node = (blockIdx.x * blockDim.x + threadIdx.x) >> 5;
    if (node >= NA) return;
    float p0 = __ldg(pos_a + 2 * node);
    float p1 = __ldg(pos_a + 2 * node + 1);
    float acc = __ldg(b1 + lane)
              + p0 * __ldg(W1 + 0 * 32 + lane)
              + p1 * __ldg(W1 + 1 * 32 + lane);
    const float4* u4 = reinterpret_cast<const float4*>(u) + node * 4;
#pragma unroll
    for (int q = 0; q < 4; ++q) {
        float4 v = __ldg(u4 + q);
        acc = fmaf(v.x, __ldg(W1 + (5 + 4 * q + 0) * 32 + lane), acc);
        acc = fmaf(v.y, __ldg(W1 + (5 + 4 * q + 1) * 32 + lane), acc);
        acc = fmaf(v.z, __ldg(W1 + (5 + 4 * q + 2) * 32 + lane), acc);
        acc = fmaf(v.w, __ldg(W1 + (5 + 4 * q + 3) * 32 + lane), acc);
    }
    g_Apre[node * 32 + lane] = acc;
}

// ---------------------------------------------------------------------------
// Per-state-node: Cpre = b1 + pos_s@W1[0:2] + h@W1[5:69]
// ---------------------------------------------------------------------------
__global__ void __launch_bounds__(256) pre_s2s_kernel(
    const float* __restrict__ pos_s,
    const float* __restrict__ h,
    const float* __restrict__ W1,
    const float* __restrict__ b1)
{
    int lane = threadIdx.x & 31;
    int node = (blockIdx.x * blockDim.x + threadIdx.x) >> 5;
    if (node >= NS) return;
    float p0 = __ldg(pos_s + 2 * node);
    float p1 = __ldg(pos_s + 2 * node + 1);
    float acc = __ldg(b1 + lane)
              + p0 * __ldg(W1 + 0 * 32 + lane)
              + p1 * __ldg(W1 + 1 * 32 + lane);
    const float4* h4 = reinterpret_cast<const float4*>(h) + node * 16;
#pragma unroll
    for (int q = 0; q < 16; ++q) {
        float4 v = __ldg(h4 + q);
        acc = fmaf(v.x, __ldg(W1 + (5 + 4 * q + 0) * 32 + lane), acc);
        acc = fmaf(v.y, __ldg(W1 + (5 + 4 * q + 1) * 32 + lane), acc);
        acc = fmaf(v.z, __ldg(W1 + (5 + 4 * q + 2) * 32 + lane), acc);
        acc = fmaf(v.w, __ldg(W1 + (5 + 4 * q + 3) * 32 + lane), acc);
    }
    g_Cpre[node * 32 + lane] = acc;
}

// ---------------------------------------------------------------------------
// Edge kernel, v2: warp handles 64 edges in two 32-edge batches.
//   Stage: hid[lane] = leaky(Asrc[s] + Bdst[d] + dis*W1[4,:]) -> smem tile
//   Inner: per edge, 16x LDS.64 (hid pairs, broadcast) + 32x fma.rn.f32x2
//          against register-resident W2 (k-pair-packed), + MUFU tanh.approx,
//          + red.global.add.v2.f32 scatter.
// NEDGE % 64 == 0, so no remainder handling.
// ---------------------------------------------------------------------------
template <int WHICH>
__global__ void __launch_bounds__(256) edge_kernel(
    const int* __restrict__ src, const int* __restrict__ dst,
    const float* __restrict__ dis,
    const float* __restrict__ W1,
    const float* __restrict__ W2,
    const float* __restrict__ b2)
{
    const float* __restrict__ Asrc = (WHICH == 0) ? g_Apre : g_Cpre;
    const float* __restrict__ Bdst = (WHICH == 0) ? g_Bpre : g_Dpre;
    float* __restrict__ sumbuf     = (WHICH == 0) ? g_sum_u : g_sum_h;

    __shared__ __align__(16) float sh[8][32 * 32];

    int lane = threadIdx.x & 31;
    int wid  = threadIdx.x >> 5;
    int warp = (blockIdx.x * blockDim.x + threadIdx.x) >> 5;
    int base = warp * 64;
    if (base >= NEDGE) return;
    float* shw = sh[wid];

    float w1d = __ldg(W1 + 4 * 32 + lane);

    // W2 repacked: w2A[kk] = {W2[2kk][2*lane], W2[2kk+1][2*lane]},
    //              w2B[kk] = {W2[2kk][2*lane+1], W2[2kk+1][2*lane+1]}
    ull w2A[16], w2B[16];
#pragma unroll
    for (int kk = 0; kk < 16; ++kk) {
        float2 r0 = __ldg(reinterpret_cast<const float2*>(W2 + (2 * kk) * 64) + lane);
        float2 r1 = __ldg(reinterpret_cast<const float2*>(W2 + (2 * kk + 1) * 64) + lane);
        w2A[kk] = pack2(r0.x, r1.x);
        w2B[kk] = pack2(r0.y, r1.y);
    }
    float b2a = __ldg(b2 + 2 * lane);
    float b2b = __ldg(b2 + 2 * lane + 1);

#pragma unroll 1
    for (int half = 0; half < 2; ++half) {
        int eidx = base + half * 32 + lane;
        int s    = __ldg(src + eidx);
        int d    = __ldg(dst + eidx);
        float dv = __ldg(dis + eidx);

        // ---- stage phase: build hid tile [32 edges][32] ----
#pragma unroll 4
        for (int t = 0; t < 32; ++t) {
            int ss   = __shfl_sync(0xffffffffu, s, t);
            int dd   = __shfl_sync(0xffffffffu, d, t);
            float dw = __shfl_sync(0xffffffffu, dv, t);
            float hid = __ldg(Asrc + ss * 32 + lane)
                      + __ldg(Bdst + dd * 32 + lane)
                      + dw * w1d;
            shw[t * 32 + lane] = leaky(hid);
        }
        __syncwarp();

        // ---- compute phase: layer-2 matmul + tanh + scatter ----
#pragma unroll 1
        for (int t = 0; t < 32; ++t) {
            int dd = __shfl_sync(0xffffffffu, d, t);
            ull accA = pack2(b2a, 0.f);
            ull accB = pack2(b2b, 0.f);
            const ull* hp = reinterpret_cast<const ull*>(shw + t * 32);
#pragma unroll
            for (int kk = 0; kk < 16; ++kk) {
                ull hpk = hp[kk];                 // LDS.64 broadcast
                accA = ffma2(hpk, w2A[kk], accA);
                accB = ffma2(hpk, w2B[kk], accB);
            }
            float a0, a1, c0, c1;
            unpack2(accA, a0, a1);
            unpack2(accB, c0, c1);
            float m0 = tanh_fast(a0 + a1);
            float m1 = tanh_fast(c0 + c1);
            float* p = sumbuf + dd * 64 + 2 * lane;
            asm volatile("red.global.add.v2.f32 [%0], {%1, %2};"
                         :: "l"(p), "f"(m0), "f"(m1) : "memory");
        }
        __syncwarp();
    }
}

// ---------------------------------------------------------------------------
// Node update: [pos_s(2), h(64), sum_u(64), sum_h(64)] -> 32 -> 64, tanh.
// Precise tanhf here (tiny cost, protects final accuracy).
// ---------------------------------------------------------------------------
__global__ void __launch_bounds__(256) upd_kernel(
    const float* __restrict__ pos_s,
    const float* __restrict__ h,
    const float* __restrict__ W1,
    const float* __restrict__ b1,
    const float* __restrict__ W2,
    const float* __restrict__ b2,
    float* __restrict__ out)
{
    int lane = threadIdx.x & 31;
    int node = (blockIdx.x * blockDim.x + threadIdx.x) >> 5;
    if (node >= NS) return;
    float p0 = __ldg(pos_s + 2 * node);
    float p1 = __ldg(pos_s + 2 * node + 1);
    float acc = __ldg(b1 + lane)
              + p0 * __ldg(W1 + 0 * 32 + lane)
              + p1 * __ldg(W1 + 1 * 32 + lane);

    const float4* h4  = reinterpret_cast<const float4*>(h) + node * 16;
    const float4* su4 = reinterpret_cast<const float4*>(g_sum_u) + node * 16;
    const float4* sh4 = reinterpret_cast<const float4*>(g_sum_h) + node * 16;
#pragma unroll
    for (int q = 0; q < 16; ++q) {
        float4 v = __ldg(h4 + q);
        acc = fmaf(v.x, __ldg(W1 + (2 + 4 * q + 0) * 32 + lane), acc);
        acc = fmaf(v.y, __ldg(W1 + (2 + 4 * q + 1) * 32 + lane), acc);
        acc = fmaf(v.z, __ldg(W1 + (2 + 4 * q + 2) * 32 + lane), acc);
        acc = fmaf(v.w, __ldg(W1 + (2 + 4 * q + 3) * 32 + lane), acc);
    }
#pragma unroll
    for (int q = 0; q < 16; ++q) {
        float4 v = su4[q];
        acc = fmaf(v.x, __ldg(W1 + (66 + 4 * q + 0) * 32 + lane), acc);
        acc = fmaf(v.y, __ldg(W1 + (66 + 4 * q + 1) * 32 + lane), acc);
        acc = fmaf(v.z, __ldg(W1 + (66 + 4 * q + 2) * 32 + lane), acc);
        acc = fmaf(v.w, __ldg(W1 + (66 + 4 * q + 3) * 32 + lane), acc);
    }
#pragma unroll
    for (int q = 0; q < 16; ++q) {
        float4 v = sh4[q];
        acc = fmaf(v.x, __ldg(W1 + (130 + 4 * q + 0) * 32 + lane), acc);
        acc = fmaf(v.y, __ldg(W1 + (130 + 4 * q + 1) * 32 + lane), acc);
        acc = fmaf(v.z, __ldg(W1 + (130 + 4 * q + 2) * 32 + lane), acc);
        acc = fmaf(v.w, __ldg(W1 + (130 + 4 * q + 3) * 32 + lane), acc);
    }
    acc = leaky(acc);

    float m0 = __ldg(b2 + 2 * lane);
    float m1 = __ldg(b2 + 2 * lane + 1);
#pragma unroll
    for (int k = 0; k < 32; ++k) {
        float hv = __shfl_sync(0xffffffffu, acc, k);
        float2 wv = __ldg(reinterpret_cast<const float2*>(W2 + k * 64) + lane);
        m0 = fmaf(hv, wv.x, m0);
        m1 = fmaf(hv, wv.y, m1);
    }
    float2 o;
    o.x = tanhf(m0);
    o.y = tanhf(m1);
    reinterpret_cast<float2*>(out)[node * 32 + lane] = o;
}

// ---------------------------------------------------------------------------
extern "C" void kernel_launch(void* const* d_in, const int* in_sizes, int n_in,
                              void* d_out, int out_size)
{
    const float* h        = (const float*)d_in[0];
    const float* u        = (const float*)d_in[1];
    const float* pos_s    = (const float*)d_in[2];
    const float* pos_a    = (const float*)d_in[3];
    const float* dis_a2s  = (const float*)d_in[4];
    const float* dis_s2s  = (const float*)d_in[5];
    const int*   a2s_src  = (const int*)d_in[6];
    const int*   a2s_dst  = (const int*)d_in[7];
    const int*   s2s_src  = (const int*)d_in[8];
    const int*   s2s_dst  = (const int*)d_in[9];
    const float* a2s_W1   = (const float*)d_in[10];
    const float* a2s_b1   = (const float*)d_in[11];
    const float* a2s_W2   = (const float*)d_in[12];
    const float* a2s_b2   = (const float*)d_in[13];
    const float* s2s_W1   = (const float*)d_in[14];
    const float* s2s_b1   = (const float*)d_in[15];
    const float* s2s_W2   = (const float*)d_in[16];
    const float* s2s_b2   = (const float*)d_in[17];
    const float* upd_W1   = (const float*)d_in[18];
    const float* upd_b1   = (const float*)d_in[19];
    const float* upd_W2   = (const float*)d_in[20];
    const float* upd_b2   = (const float*)d_in[21];
    float* out = (float*)d_out;

    const int WPB = 8;  // warps per block (256 threads)

    pre_s_kernel  <<<(NS + WPB - 1) / WPB, 256>>>(pos_s, a2s_W1, s2s_W1);
    pre_a2s_kernel<<<(NA + WPB - 1) / WPB, 256>>>(pos_a, u, a2s_W1, a2s_b1);
    pre_s2s_kernel<<<(NS + WPB - 1) / WPB, 256>>>(pos_s, h, s2s_W1, s2s_b1);

    const int CHUNK = 64;
    int nwarps = NEDGE / CHUNK;                 // 25000
    int eblocks = (nwarps + WPB - 1) / WPB;     // 3125
    edge_kernel<0><<<eblocks, 256>>>(a2s_src, a2s_dst, dis_a2s, a2s_W1, a2s_W2, a2s_b2);
    edge_kernel<1><<<eblocks, 256>>>(s2s_src, s2s_dst, dis_s2s, s2s_W1, s2s_W2, s2s_b2);

    upd_kernel<<<(NS + WPB - 1) / WPB, 256>>>(pos_s, h, upd_W1, upd_b1, upd_W2, upd_b2, out);
}

// round 3
// speedup vs baseline: 1.5231x; 1.0585x over previous
#include <cuda_runtime.h>
#include <math.h>

#define NS 50000
#define NA 50000
#define NEDGE 1600000

typedef unsigned long long ull;

// Scratch (device globals; no allocation allowed)
__device__ __align__(16) float g_Apre[NA * 32];   // a2s src-side layer1 partial (+b1)
__device__ __align__(16) float g_Bpre[NS * 32];   // a2s dst-side layer1 partial
__device__ __align__(16) float g_Cpre[NS * 32];   // s2s src-side layer1 partial (+b1)
__device__ __align__(16) float g_Dpre[NS * 32];   // s2s dst-side layer1 partial
__device__ __align__(16) float g_sum_u[NS * 64];
__device__ __align__(16) float g_sum_h[NS * 64];

__device__ __forceinline__ float leaky(float x) { return fmaxf(x, 0.01f * x); }

__device__ __forceinline__ ull pack2(float x, float y) {
    ull r; asm("mov.b64 %0, {%1, %2};" : "=l"(r) : "f"(x), "f"(y)); return r;
}
__device__ __forceinline__ void unpack2(ull v, float& x, float& y) {
    asm("mov.b64 {%0, %1}, %2;" : "=f"(x), "=f"(y) : "l"(v));
}
__device__ __forceinline__ ull ffma2(ull a, ull b, ull c) {
    ull r; asm("fma.rn.f32x2 %0, %1, %2, %3;" : "=l"(r) : "l"(a), "l"(b), "l"(c)); return r;
}
__device__ __forceinline__ float tanh_fast(float x) {
    float r; asm("tanh.approx.f32 %0, %1;" : "=f"(r) : "f"(x)); return r;
}

// ---------------------------------------------------------------------------
// Fused node-side precompute. Warp-task id t over [0, NS + NA + NS):
//   t in [0,NS):          Bpre/Dpre from pos_s, zero sum bufs
//   t in [NS,NS+NA):      Apre = b1 + pos_a@W1[0:2] + u@W1[5:21]
//   t in [NS+NA, 2NS+NA): Cpre = b1 + pos_s@W1[0:2] + h@W1[5:69]
// ---------------------------------------------------------------------------
__global__ void __launch_bounds__(256) pre_kernel(
    const float* __restrict__ pos_s,
    const float* __restrict__ pos_a,
    const float* __restrict__ u,
    const float* __restrict__ h,
    const float* __restrict__ a2s_W1, const float* __restrict__ a2s_b1,
    const float* __restrict__ s2s_W1, const float* __restrict__ s2s_b1)
{
    int lane = threadIdx.x & 31;
    int task = (blockIdx.x * blockDim.x + threadIdx.x) >> 5;

    if (task < NS) {
        int node = task;
        float p0 = __ldg(pos_s + 2 * node);
        float p1 = __ldg(pos_s + 2 * node + 1);
        g_Bpre[node * 32 + lane] =
            p0 * __ldg(a2s_W1 + 2 * 32 + lane) + p1 * __ldg(a2s_W1 + 3 * 32 + lane);
        g_Dpre[node * 32 + lane] =
            p0 * __ldg(s2s_W1 + 2 * 32 + lane) + p1 * __ldg(s2s_W1 + 3 * 32 + lane);
        g_sum_u[node * 64 + lane]      = 0.f;
        g_sum_u[node * 64 + 32 + lane] = 0.f;
        g_sum_h[node * 64 + lane]      = 0.f;
        g_sum_h[node * 64 + 32 + lane] = 0.f;
    } else if (task < NS + NA) {
        int node = task - NS;
        const float* W1 = a2s_W1;
        float p0 = __ldg(pos_a + 2 * node);
        float p1 = __ldg(pos_a + 2 * node + 1);
        float acc = __ldg(a2s_b1 + lane)
                  + p0 * __ldg(W1 + 0 * 32 + lane)
                  + p1 * __ldg(W1 + 1 * 32 + lane);
        const float4* u4 = reinterpret_cast<const float4*>(u) + node * 4;
#pragma unroll
        for (int q = 0; q < 4; ++q) {
            float4 v = __ldg(u4 + q);
            acc = fmaf(v.x, __ldg(W1 + (5 + 4 * q + 0) * 32 + lane), acc);
            acc = fmaf(v.y, __ldg(W1 + (5 + 4 * q + 1) * 32 + lane), acc);
            acc = fmaf(v.z, __ldg(W1 + (5 + 4 * q + 2) * 32 + lane), acc);
            acc = fmaf(v.w, __ldg(W1 + (5 + 4 * q + 3) * 32 + lane), acc);
        }
        g_Apre[node * 32 + lane] = acc;
    } else if (task < NS + NA + NS) {
        int node = task - NS - NA;
        const float* W1 = s2s_W1;
        float p0 = __ldg(pos_s + 2 * node);
        float p1 = __ldg(pos_s + 2 * node + 1);
        float acc = __ldg(s2s_b1 + lane)
                  + p0 * __ldg(W1 + 0 * 32 + lane)
                  + p1 * __ldg(W1 + 1 * 32 + lane);
        const float4* h4 = reinterpret_cast<const float4*>(h) + node * 16;
#pragma unroll
        for (int q = 0; q < 16; ++q) {
            float4 v = __ldg(h4 + q);
            acc = fmaf(v.x, __ldg(W1 + (5 + 4 * q + 0) * 32 + lane), acc);
            acc = fmaf(v.y, __ldg(W1 + (5 + 4 * q + 1) * 32 + lane), acc);
            acc = fmaf(v.z, __ldg(W1 + (5 + 4 * q + 2) * 32 + lane), acc);
            acc = fmaf(v.w, __ldg(W1 + (5 + 4 * q + 3) * 32 + lane), acc);
        }
        g_Cpre[node * 32 + lane] = acc;
    }
}

// ---------------------------------------------------------------------------
// Fused edge kernel: blocks [0, EB) handle a2s, [EB, 2*EB) handle s2s.
// Warp handles 64 edges in two 32-edge batches:
//   Stage:  hid tile [32][32] -> smem (leaky(Asrc + Bdst + dis*w1d))
//   Compute: 2 edges interleaved; per pair 16x LDS.128 + 32x fma.rn.f32x2
//            against register-resident W2, MUFU tanh.approx, RED.v2 scatter.
// NEDGE % 64 == 0.
// ---------------------------------------------------------------------------
__global__ void __launch_bounds__(256, 2) edge_kernel(
    int eb,
    const int* __restrict__ src0, const int* __restrict__ dst0,
    const float* __restrict__ dis0,
    const float* __restrict__ W10, const float* __restrict__ W20,
    const float* __restrict__ b20,
    const int* __restrict__ src1, const int* __restrict__ dst1,
    const float* __restrict__ dis1,
    const float* __restrict__ W11, const float* __restrict__ W21,
    const float* __restrict__ b21)
{
    bool second = (blockIdx.x >= (unsigned)eb);
    int blk = second ? (blockIdx.x - eb) : blockIdx.x;

    const int*   src = second ? src1 : src0;
    const int*   dst = second ? dst1 : dst0;
    const float* dis = second ? dis1 : dis0;
    const float* W1  = second ? W11  : W10;
    const float* W2  = second ? W21  : W20;
    const float* b2  = second ? b21  : b20;
    const float* __restrict__ Asrc = second ? g_Cpre : g_Apre;
    const float* __restrict__ Bdst = second ? g_Dpre : g_Bpre;
    float* __restrict__ sumbuf     = second ? g_sum_h : g_sum_u;

    __shared__ __align__(16) float sh[8][32 * 32];

    int lane = threadIdx.x & 31;
    int wid  = threadIdx.x >> 5;
    int base = (blk * 8 + wid) * 64;
    float* shw = sh[wid];

    float w1d = __ldg(W1 + 4 * 32 + lane);

    // W2 repacked over k-pairs: w2A -> col 2*lane, w2B -> col 2*lane+1
    ull w2A[16], w2B[16];
#pragma unroll
    for (int kk = 0; kk < 16; ++kk) {
        float2 r0 = __ldg(reinterpret_cast<const float2*>(W2 + (2 * kk) * 64) + lane);
        float2 r1 = __ldg(reinterpret_cast<const float2*>(W2 + (2 * kk + 1) * 64) + lane);
        w2A[kk] = pack2(r0.x, r1.x);
        w2B[kk] = pack2(r0.y, r1.y);
    }
    ull biasA, biasB;
    {
        float b2a = __ldg(b2 + 2 * lane);
        float b2b = __ldg(b2 + 2 * lane + 1);
        biasA = pack2(b2a, 0.f);
        biasB = pack2(b2b, 0.f);
    }

#pragma unroll 1
    for (int half = 0; half < 2; ++half) {
        int eidx = base + half * 32 + lane;
        int s    = __ldg(src + eidx);
        int d    = __ldg(dst + eidx);
        float dv = __ldg(dis + eidx);

        // ---- stage phase: hid tile [32 edges][32] ----
#pragma unroll 4
        for (int t = 0; t < 32; ++t) {
            int ss   = __shfl_sync(0xffffffffu, s, t);
            int dd   = __shfl_sync(0xffffffffu, d, t);
            float dw = __shfl_sync(0xffffffffu, dv, t);
            float hid = __ldg(Asrc + ss * 32 + lane)
                      + __ldg(Bdst + dd * 32 + lane)
                      + dw * w1d;
            shw[t * 32 + lane] = leaky(hid);
        }
        __syncwarp();

        // ---- compute phase: 2 edges interleaved ----
#pragma unroll 1
        for (int t = 0; t < 32; t += 2) {
            int dd0 = __shfl_sync(0xffffffffu, d, t);
            int dd1 = __shfl_sync(0xffffffffu, d, t + 1);
            const ulonglong2* h0 = reinterpret_cast<const ulonglong2*>(shw + t * 32);
            const ulonglong2* h1 = reinterpret_cast<const ulonglong2*>(shw + (t + 1) * 32);
            ull a0 = biasA, b0 = biasB, a1 = biasA, b1 = biasB;
#pragma unroll
            for (int q = 0; q < 8; ++q) {
                ulonglong2 x0 = h0[q];           // LDS.128 broadcast
                ulonglong2 x1 = h1[q];
                a0 = ffma2(x0.x, w2A[2 * q], a0);
                b0 = ffma2(x0.x, w2B[2 * q], b0);
                a0 = ffma2(x0.y, w2A[2 * q + 1], a0);
                b0 = ffma2(x0.y, w2B[2 * q + 1], b0);
                a1 = ffma2(x1.x, w2A[2 * q], a1);
                b1 = ffma2(x1.x, w2B[2 * q], b1);
                a1 = ffma2(x1.y, w2A[2 * q + 1], a1);
                b1 = ffma2(x1.y, w2B[2 * q + 1], b1);
            }
            float p0, p1, q0, q1, r0, r1, s0, s1;
            unpack2(a0, p0, p1);
            unpack2(b0, q0, q1);
            unpack2(a1, r0, r1);
            unpack2(b1, s0, s1);
            float m00 = tanh_fast(p0 + p1);
            float m01 = tanh_fast(q0 + q1);
            float m10 = tanh_fast(r0 + r1);
            float m11 = tanh_fast(s0 + s1);
            float* pA = sumbuf + dd0 * 64 + 2 * lane;
            float* pB = sumbuf + dd1 * 64 + 2 * lane;
            asm volatile("red.global.add.v2.f32 [%0], {%1, %2};"
                         :: "l"(pA), "f"(m00), "f"(m01) : "memory");
            asm volatile("red.global.add.v2.f32 [%0], {%1, %2};"
                         :: "l"(pB), "f"(m10), "f"(m11) : "memory");
        }
        __syncwarp();
    }
}

// ---------------------------------------------------------------------------
// Node update: [pos_s(2), h(64), sum_u(64), sum_h(64)] -> 32 -> 64, tanh.
// Precise tanhf here (tiny cost, protects final accuracy).
// ---------------------------------------------------------------------------
__global__ void __launch_bounds__(256) upd_kernel(
    const float* __restrict__ pos_s,
    const float* __restrict__ h,
    const float* __restrict__ W1,
    const float* __restrict__ b1,
    const float* __restrict__ W2,
    const float* __restrict__ b2,
    float* __restrict__ out)
{
    int lane = threadIdx.x & 31;
    int node = (blockIdx.x * blockDim.x + threadIdx.x) >> 5;
    if (node >= NS) return;
    float p0 = __ldg(pos_s + 2 * node);
    float p1 = __ldg(pos_s + 2 * node + 1);
    float acc = __ldg(b1 + lane)
              + p0 * __ldg(W1 + 0 * 32 + lane)
              + p1 * __ldg(W1 + 1 * 32 + lane);

    const float4* h4  = reinterpret_cast<const float4*>(h) + node * 16;
    const float4* su4 = reinterpret_cast<const float4*>(g_sum_u) + node * 16;
    const float4* sh4 = reinterpret_cast<const float4*>(g_sum_h) + node * 16;
#pragma unroll
    for (int q = 0; q < 16; ++q) {
        float4 v = __ldg(h4 + q);
        acc = fmaf(v.x, __ldg(W1 + (2 + 4 * q + 0) * 32 + lane), acc);
        acc = fmaf(v.y, __ldg(W1 + (2 + 4 * q + 1) * 32 + lane), acc);
        acc = fmaf(v.z, __ldg(W1 + (2 + 4 * q + 2) * 32 + lane), acc);
        acc = fmaf(v.w, __ldg(W1 + (2 + 4 * q + 3) * 32 + lane), acc);
    }
#pragma unroll
    for (int q = 0; q < 16; ++q) {
        float4 v = su4[q];
        acc = fmaf(v.x, __ldg(W1 + (66 + 4 * q + 0) * 32 + lane), acc);
        acc = fmaf(v.y, __ldg(W1 + (66 + 4 * q + 1) * 32 + lane), acc);
        acc = fmaf(v.z, __ldg(W1 + (66 + 4 * q + 2) * 32 + lane), acc);
        acc = fmaf(v.w, __ldg(W1 + (66 + 4 * q + 3) * 32 + lane), acc);
    }
#pragma unroll
    for (int q = 0; q < 16; ++q) {
        float4 v = sh4[q];
        acc = fmaf(v.x, __ldg(W1 + (130 + 4 * q + 0) * 32 + lane), acc);
        acc = fmaf(v.y, __ldg(W1 + (130 + 4 * q + 1) * 32 + lane), acc);
        acc = fmaf(v.z, __ldg(W1 + (130 + 4 * q + 2) * 32 + lane), acc);
        acc = fmaf(v.w, __ldg(W1 + (130 + 4 * q + 3) * 32 + lane), acc);
    }
    acc = leaky(acc);

    float m0 = __ldg(b2 + 2 * lane);
    float m1 = __ldg(b2 + 2 * lane + 1);
#pragma unroll
    for (int k = 0; k < 32; ++k) {
        float hv = __shfl_sync(0xffffffffu, acc, k);
        float2 wv = __ldg(reinterpret_cast<const float2*>(W2 + k * 64) + lane);
        m0 = fmaf(hv, wv.x, m0);
        m1 = fmaf(hv, wv.y, m1);
    }
    float2 o;
    o.x = tanhf(m0);
    o.y = tanhf(m1);
    reinterpret_cast<float2*>(out)[node * 32 + lane] = o;
}

// ---------------------------------------------------------------------------
extern "C" void kernel_launch(void* const* d_in, const int* in_sizes, int n_in,
                              void* d_out, int out_size)
{
    const float* h        = (const float*)d_in[0];
    const float* u        = (const float*)d_in[1];
    const float* pos_s    = (const float*)d_in[2];
    const float* pos_a    = (const float*)d_in[3];
    const float* dis_a2s  = (const float*)d_in[4];
    const float* dis_s2s  = (const float*)d_in[5];
    const int*   a2s_src  = (const int*)d_in[6];
    const int*   a2s_dst  = (const int*)d_in[7];
    const int*   s2s_src  = (const int*)d_in[8];
    const int*   s2s_dst  = (const int*)d_in[9];
    const float* a2s_W1   = (const float*)d_in[10];
    const float* a2s_b1   = (const float*)d_in[11];
    const float* a2s_W2   = (const float*)d_in[12];
    const float* a2s_b2   = (const float*)d_in[13];
    const float* s2s_W1   = (const float*)d_in[14];
    const float* s2s_b1   = (const float*)d_in[15];
    const float* s2s_W2   = (const float*)d_in[16];
    const float* s2s_b2   = (const float*)d_in[17];
    const float* upd_W1   = (const float*)d_in[18];
    const float* upd_b1   = (const float*)d_in[19];
    const float* upd_W2   = (const float*)d_in[20];
    const float* upd_b2   = (const float*)d_in[21];
    float* out = (float*)d_out;

    const int WPB = 8;  // warps per block (256 threads)

    // Fused node-side precompute
    int pre_tasks = NS + NA + NS;
    pre_kernel<<<(pre_tasks + WPB - 1) / WPB, 256>>>(
        pos_s, pos_a, u, h, a2s_W1, a2s_b1, s2s_W1, s2s_b1);

    // Fused edge passes (first eb blocks: a2s; next eb: s2s)
    int eb = (NEDGE / 64 + WPB - 1) / WPB;   // 3125
    edge_kernel<<<2 * eb, 256>>>(
        eb,
        a2s_src, a2s_dst, dis_a2s, a2s_W1, a2s_W2, a2s_b2,
        s2s_src, s2s_dst, dis_s2s, s2s_W1, s2s_W2, s2s_b2);

    // Node update
    upd_kernel<<<(NS + WPB - 1) / WPB, 256>>>(pos_s, h, upd_W1, upd_b1, upd_W2, upd_b2, out);
}